// round 2
// baseline (speedup 1.0000x reference)
#include <cuda_runtime.h>
#include <math.h>

// Problem constants
#define B_ 16
#define L_ 512
#define D_ 768
#define H_ 12
#define K_ 128
#define U_ 256
#define NH_ 4
#define HD_ 64

static __device__ __align__(16) float g_importance[B_*L_];
static __device__ __align__(16) float g_sent[B_*D_];
static __device__ __align__(16) float g_t[B_*NH_*D_];
static __device__ __align__(16) float g_scores[B_*NH_*L_];
static __device__ __align__(16) float g_w[B_*NH_*D_];
static __device__ __align__(16) float g_newtok[B_*D_];
static __device__ int   g_idx[B_*K_];

__device__ __forceinline__ float warp_max(float v){
  #pragma unroll
  for (int o=16;o;o>>=1) v = fmaxf(v, __shfl_xor_sync(0xffffffffu, v, o));
  return v;
}
__device__ __forceinline__ float warp_sum(float v){
  #pragma unroll
  for (int o=16;o;o>>=1) v += __shfl_xor_sync(0xffffffffu, v, o);
  return v;
}
// Block-wide reductions across nw warps. red >= nw floats. Broadcast result.
__device__ __forceinline__ float block_max(float v, float* red, int wid, int lane, int nw){
  v = warp_max(v);
  if (lane==0) red[wid] = v;
  __syncthreads();
  if (wid==0){
    float x = (lane < nw) ? red[lane] : -INFINITY;
    x = warp_max(x);
    if (lane==0) red[0] = x;
  }
  __syncthreads();
  float r = red[0];
  __syncthreads();
  return r;
}
__device__ __forceinline__ float block_sum(float v, float* red, int wid, int lane, int nw){
  v = warp_sum(v);
  if (lane==0) red[wid] = v;
  __syncthreads();
  if (wid==0){
    float x = (lane < nw) ? red[lane] : 0.f;
    x = warp_sum(x);
    if (lane==0) red[0] = x;
  }
  __syncthreads();
  float r = red[0];
  __syncthreads();
  return r;
}

// ---------------------------------------------------------------------------
// Zero accumulators (required every graph replay)
__global__ void __launch_bounds__(256) k_init(){
  int i = blockIdx.x*blockDim.x + threadIdx.x;
  if (i < B_*L_)     g_importance[i] = 0.f;
  if (i < B_*D_)     g_sent[i] = 0.f;
  if (i < B_*NH_*D_) g_w[i] = 0.f;
}

// ---------------------------------------------------------------------------
// importance[b,l] = (1/H) * sum_{h,q} scores[b,h,q,l]   (201 MB streaming reduce)
// grid (B, 96) : each block sums 64 of the 6144 (h,q) rows. 256 threads:
//   threadIdx & 127 -> float4 column, threadIdx >> 7 -> row parity.
__global__ void __launch_bounds__(256) k_importance(const float* __restrict__ s){
  int b = blockIdx.x, ch = blockIdx.y;
  int col = threadIdx.x & 127;
  int rh  = threadIdx.x >> 7;
  const float4* base = (const float4*)s + (size_t)(b*H_*L_ + ch*64) * (L_/4);
  float4 acc = make_float4(0.f,0.f,0.f,0.f);
  #pragma unroll 8
  for (int r = rh; r < 64; r += 2){
    float4 v = base[(size_t)r*(L_/4) + col];
    acc.x += v.x; acc.y += v.y; acc.z += v.z; acc.w += v.w;
  }
  const float sc = 1.0f/(float)H_;
  float* out = g_importance + b*L_ + col*4;
  atomicAdd(out+0, acc.x*sc);
  atomicAdd(out+1, acc.y*sc);
  atomicAdd(out+2, acc.z*sc);
  atomicAdd(out+3, acc.w*sc);
}

// ---------------------------------------------------------------------------
// sentences[b,d] = sum_l softmax(mask[b,:])[l] * hidden[b,l,d]
// grid (B, 8), 768 threads; each block handles 64 l's, atomic accumulate.
__global__ void __launch_bounds__(768) k_sentences(const float* __restrict__ hs,
                                                   const float* __restrict__ mask){
  __shared__ float s_att[L_];
  __shared__ float red[32];
  int b = blockIdx.x, ch = blockIdx.y;
  int tid = threadIdx.x, wid = tid>>5, lane = tid&31;
  float mv = (tid < L_) ? mask[b*L_ + tid] : -3.0e38f;
  float m = block_max(mv, red, wid, lane, 24);
  float e = (tid < L_) ? expf(mv - m) : 0.f;
  float ssum = block_sum(e, red, wid, lane, 24);
  if (tid < L_) s_att[tid] = e / ssum;
  __syncthreads();
  float acc = 0.f;
  int l0 = ch*64;
  const float* hb = hs + ((size_t)b*L_ + l0)*D_ + tid;
  #pragma unroll 4
  for (int l = 0; l < 64; l++)
    acc += s_att[l0+l] * hb[(size_t)l*D_];
  atomicAdd(&g_sent[b*D_ + tid], acc);
}

// ---------------------------------------------------------------------------
// q[b,u] = sentences[b]·Wq[u,:];  t[b,h,d] = sum_j q[b,h*64+j]*Wk[h*64+j,d]
// grid B, 768 threads
__global__ void __launch_bounds__(768) k_qt(const float* __restrict__ Wq,
                                            const float* __restrict__ Wk){
  __shared__ float s_sent[D_];
  __shared__ float s_q[U_];
  int b = blockIdx.x, tid = threadIdx.x, wid = tid>>5, lane = tid&31;
  s_sent[tid] = g_sent[b*D_ + tid];
  __syncthreads();
  for (int u = wid; u < U_; u += 24){
    const float* wr = Wq + (size_t)u*D_;
    float acc = 0.f;
    #pragma unroll 6
    for (int k = lane; k < D_; k += 32) acc += s_sent[k]*wr[k];
    acc = warp_sum(acc);
    if (lane==0) s_q[u] = acc;
  }
  __syncthreads();
  #pragma unroll
  for (int h = 0; h < NH_; h++){
    float acc = 0.f;
    #pragma unroll 8
    for (int j = 0; j < HD_; j++)
      acc += s_q[h*HD_+j] * Wk[(size_t)(h*HD_+j)*D_ + tid];
    g_t[(b*NH_+h)*D_ + tid] = acc;
  }
}

// ---------------------------------------------------------------------------
// scores[b,h,l] = (t[b,h]·hidden[b,l]) / sqrt(D), masked -> -inf
// grid (B, 8), 512 threads; warp per l (each warp does 4 l's)
__global__ void __launch_bounds__(512) k_scores(const float* __restrict__ hs,
                                                const float* __restrict__ mask){
  __shared__ __align__(16) float s_t[NH_*D_];
  int b = blockIdx.x, ch = blockIdx.y;
  int tid = threadIdx.x, wid = tid>>5, lane = tid&31;
  for (int i = tid; i < NH_*D_; i += 512) s_t[i] = g_t[b*NH_*D_ + i];
  __syncthreads();
  const float4* t4 = (const float4*)s_t;
  const float inv_sqrt_d = 0.03608439182435161f; // 1/sqrt(768)
  #pragma unroll
  for (int li = 0; li < 4; li++){
    int l = ch*64 + wid*4 + li;
    const float4* hr = (const float4*)(hs + ((size_t)b*L_ + l)*D_);
    float a0=0.f,a1=0.f,a2=0.f,a3=0.f;
    #pragma unroll
    for (int k = 0; k < 6; k++){
      float4 v  = hr[lane + 32*k];
      float4 t0 = t4[0*192 + lane + 32*k];
      float4 t1 = t4[1*192 + lane + 32*k];
      float4 t2 = t4[2*192 + lane + 32*k];
      float4 t3 = t4[3*192 + lane + 32*k];
      a0 += v.x*t0.x + v.y*t0.y + v.z*t0.z + v.w*t0.w;
      a1 += v.x*t1.x + v.y*t1.y + v.z*t1.z + v.w*t1.w;
      a2 += v.x*t2.x + v.y*t2.y + v.z*t2.z + v.w*t2.w;
      a3 += v.x*t3.x + v.y*t3.y + v.z*t3.z + v.w*t3.w;
    }
    a0 = warp_sum(a0); a1 = warp_sum(a1); a2 = warp_sum(a2); a3 = warp_sum(a3);
    if (lane == 0){
      bool pad = mask[b*L_ + l] < -10.f;
      g_scores[(b*NH_+0)*L_ + l] = pad ? -INFINITY : a0*inv_sqrt_d;
      g_scores[(b*NH_+1)*L_ + l] = pad ? -INFINITY : a1*inv_sqrt_d;
      g_scores[(b*NH_+2)*L_ + l] = pad ? -INFINITY : a2*inv_sqrt_d;
      g_scores[(b*NH_+3)*L_ + l] = pad ? -INFINITY : a3*inv_sqrt_d;
    }
  }
}

// ---------------------------------------------------------------------------
// softmax over l per (b,h), then w[b,h,d] += sum_{l in chunk} p[l]*hidden[b,l,d]
// grid (B, 8), 768 threads. Softmax recomputed per block (cheap, deterministic).
__global__ void __launch_bounds__(768) k_wacc(const float* __restrict__ hs){
  __shared__ float s_p[NH_*L_];
  __shared__ float red[32];
  int b = blockIdx.x, ch = blockIdx.y;
  int tid = threadIdx.x, wid = tid>>5, lane = tid&31;
  #pragma unroll
  for (int h = 0; h < NH_; h++){
    float v = (tid < L_) ? g_scores[(b*NH_+h)*L_ + tid] : -INFINITY;
    float m = block_max(v, red, wid, lane, 24);
    float e = (tid < L_) ? expf(v - m) : 0.f;
    float ssum = block_sum(e, red, wid, lane, 24);
    if (tid < L_) s_p[h*L_ + tid] = e / ssum;
  }
  __syncthreads();
  float a0=0.f,a1=0.f,a2=0.f,a3=0.f;
  int l0 = ch*64;
  const float* hb = hs + ((size_t)b*L_ + l0)*D_ + tid;
  #pragma unroll 2
  for (int l = 0; l < 64; l++){
    float hv = hb[(size_t)l*D_];
    a0 += s_p[0*L_ + l0+l]*hv;
    a1 += s_p[1*L_ + l0+l]*hv;
    a2 += s_p[2*L_ + l0+l]*hv;
    a3 += s_p[3*L_ + l0+l]*hv;
  }
  atomicAdd(&g_w[(b*NH_+0)*D_ + tid], a0);
  atomicAdd(&g_w[(b*NH_+1)*D_ + tid], a1);
  atomicAdd(&g_w[(b*NH_+2)*D_ + tid], a2);
  atomicAdd(&g_w[(b*NH_+3)*D_ + tid], a3);
}

// ---------------------------------------------------------------------------
// out[b,u]= w[b,h(u)]·Wv[u,:] ; new_token[b,d] = out[b,:]·Wo[d,:] + bo[d]
// grid B, 768 threads
__global__ void __launch_bounds__(768) k_out(const float* __restrict__ Wv,
                                             const float* __restrict__ Wo,
                                             const float* __restrict__ bo){
  __shared__ float s_w[NH_*D_];
  __shared__ float s_o[U_];
  int b = blockIdx.x, tid = threadIdx.x, wid = tid>>5, lane = tid&31;
  for (int i = tid; i < NH_*D_; i += 768) s_w[i] = g_w[b*NH_*D_ + i];
  __syncthreads();
  for (int u = wid; u < U_; u += 24){
    int h = u >> 6;
    const float* vr = Wv + (size_t)u*D_;
    float acc = 0.f;
    #pragma unroll 6
    for (int k = lane; k < D_; k += 32) acc += s_w[h*D_ + k]*vr[k];
    acc = warp_sum(acc);
    if (lane==0) s_o[u] = acc;
  }
  __syncthreads();
  for (int d = wid; d < D_; d += 24){
    const float* wr = Wo + (size_t)d*U_;
    float acc = 0.f;
    #pragma unroll
    for (int k = lane; k < U_; k += 32) acc += s_o[k]*wr[k];
    acc = warp_sum(acc);
    if (lane==0) g_newtok[b*D_ + d] = acc + bo[d];
  }
}

// ---------------------------------------------------------------------------
// top-K by rank with jax tie rule (greater value wins; ties -> lower index),
// output compacted by index => already index-sorted. grid B, 512 threads.
__global__ void __launch_bounds__(512) k_topk(){
  __shared__ float v[L_];
  __shared__ int flag[L_];
  int b = blockIdx.x, tid = threadIdx.x;
  v[tid] = g_importance[b*L_ + tid];
  __syncthreads();
  float mv = v[tid];
  int r = 0;
  #pragma unroll 8
  for (int j = 0; j < L_; j++){
    float o = v[j];
    r += (o > mv) || (o == mv && j < tid);
  }
  int sel = (r < K_) ? 1 : 0;
  flag[tid] = sel;
  __syncthreads();
  if (sel){
    int pos = 0;
    for (int j = 0; j < tid; j++) pos += flag[j];
    g_idx[b*K_ + pos] = tid;
  }
}

// ---------------------------------------------------------------------------
// Assemble: final_token (B,130,768) then final_attention_mask (B,130).
// grid B*130, 192 threads (float4 rows).
__global__ void __launch_bounds__(192) k_assemble(const float* __restrict__ hs,
                                                  const float* __restrict__ mask,
                                                  float* __restrict__ out){
  int r = blockIdx.x % 130;
  int b = blockIdx.x / 130;
  int tid = threadIdx.x;
  const float* src;
  float mval = 0.f;
  if (r == 0){
    src = hs + (size_t)b*L_*D_;
  } else if (r < 129){
    int idx = g_idx[b*K_ + r - 1];
    src = hs + ((size_t)b*L_ + idx)*D_;
    mval = mask[b*L_ + idx];
  } else {
    src = g_newtok + b*D_;
  }
  float4 val = ((const float4*)src)[tid];
  ((float4*)(out + (size_t)(b*130 + r)*D_))[tid] = val;
  if (tid == 0) out[(size_t)B_*130*D_ + b*130 + r] = mval;
}

// ---------------------------------------------------------------------------
extern "C" void kernel_launch(void* const* d_in, const int* in_sizes, int n_in,
                              void* d_out, int out_size) {
  const float* hs   = (const float*)d_in[0]; // hidden_states (B,L,D)
  const float* mask = (const float*)d_in[1]; // attention_mask (B,1,1,L)
  const float* sas  = (const float*)d_in[2]; // self_attention_scores (B,H,L,L)
  const float* Wq   = (const float*)d_in[3];
  const float* Wk   = (const float*)d_in[4];
  const float* Wv   = (const float*)d_in[5];
  const float* Wo   = (const float*)d_in[6];
  const float* bo   = (const float*)d_in[7];
  float* out = (float*)d_out;

  k_init<<<192, 256>>>();
  k_importance<<<dim3(B_, 96), 256>>>(sas);
  k_sentences<<<dim3(B_, 8), 768>>>(hs, mask);
  k_qt<<<B_, 768>>>(Wq, Wk);
  k_scores<<<dim3(B_, 8), 512>>>(hs, mask);
  k_wacc<<<dim3(B_, 8), 768>>>(hs);
  k_out<<<B_, 768>>>(Wv, Wo, bo);
  k_topk<<<B_, 512>>>();
  k_assemble<<<B_*130, 192>>>(hs, mask, out);
}

// round 3
// speedup vs baseline: 1.3479x; 1.3479x over previous
#include <cuda_runtime.h>
#include <math.h>

// Problem constants
#define B_ 16
#define L_ 512
#define D_ 768
#define H_ 12
#define K_ 128
#define U_ 256
#define NH_ 4
#define HD_ 64

static __device__ __align__(16) float g_importance[B_*L_];
static __device__ __align__(16) float g_sent[B_*D_];
static __device__ __align__(16) float g_q[B_*U_];
static __device__ __align__(16) float g_t[B_*NH_*D_];
static __device__ __align__(16) float g_scores[B_*NH_*L_];
static __device__ __align__(16) float g_p[B_*NH_*L_];
static __device__ __align__(16) float g_w[B_*NH_*D_];
static __device__ __align__(16) float g_o[B_*U_];
static __device__ __align__(16) float g_newtok[B_*D_];
static __device__ int   g_idx[B_*K_];

__device__ __forceinline__ float warp_max(float v){
  #pragma unroll
  for (int o=16;o;o>>=1) v = fmaxf(v, __shfl_xor_sync(0xffffffffu, v, o));
  return v;
}
__device__ __forceinline__ float warp_sum(float v){
  #pragma unroll
  for (int o=16;o;o>>=1) v += __shfl_xor_sync(0xffffffffu, v, o);
  return v;
}
__device__ __forceinline__ float block_max(float v, float* red, int wid, int lane, int nw){
  v = warp_max(v);
  if (lane==0) red[wid] = v;
  __syncthreads();
  if (wid==0){
    float x = (lane < nw) ? red[lane] : -INFINITY;
    x = warp_max(x);
    if (lane==0) red[0] = x;
  }
  __syncthreads();
  float r = red[0];
  __syncthreads();
  return r;
}
__device__ __forceinline__ float block_sum(float v, float* red, int wid, int lane, int nw){
  v = warp_sum(v);
  if (lane==0) red[wid] = v;
  __syncthreads();
  if (wid==0){
    float x = (lane < nw) ? red[lane] : 0.f;
    x = warp_sum(x);
    if (lane==0) red[0] = x;
  }
  __syncthreads();
  float r = red[0];
  __syncthreads();
  return r;
}

// ---------------------------------------------------------------------------
// Zero accumulators (required every graph replay)
__global__ void __launch_bounds__(256) k_init(){
  int i = blockIdx.x*blockDim.x + threadIdx.x;
  if (i < B_*L_)     g_importance[i] = 0.f;
  if (i < B_*D_)     g_sent[i] = 0.f;
  if (i < B_*NH_*D_) g_w[i] = 0.f;
}

// ---------------------------------------------------------------------------
// importance[b,l] = (1/H) * sum_{h,q} scores[b,h,q,l]   (201 MB streaming reduce)
// grid (B, 96): each block sums 64 of the 6144 (h,q) rows.
__global__ void __launch_bounds__(256) k_importance(const float* __restrict__ s){
  int b = blockIdx.x, ch = blockIdx.y;
  int col = threadIdx.x & 127;
  int rh  = threadIdx.x >> 7;
  const float4* base = (const float4*)s + (size_t)(b*H_*L_ + ch*64) * (L_/4);
  float4 acc = make_float4(0.f,0.f,0.f,0.f);
  #pragma unroll 8
  for (int r = rh; r < 64; r += 2){
    float4 v = base[(size_t)r*(L_/4) + col];
    acc.x += v.x; acc.y += v.y; acc.z += v.z; acc.w += v.w;
  }
  const float sc = 1.0f/(float)H_;
  float* out = g_importance + b*L_ + col*4;
  atomicAdd(out+0, acc.x*sc);
  atomicAdd(out+1, acc.y*sc);
  atomicAdd(out+2, acc.z*sc);
  atomicAdd(out+3, acc.w*sc);
}

// ---------------------------------------------------------------------------
// sentences[b,d] = sum_l softmax(mask[b,:])[l] * hidden[b,l,d]
// grid (B, 16), 768 threads; each block handles 32 l's, atomic accumulate.
__global__ void __launch_bounds__(768) k_sentences(const float* __restrict__ hs,
                                                   const float* __restrict__ mask){
  __shared__ float s_att[L_];
  __shared__ float red[32];
  int b = blockIdx.x, ch = blockIdx.y;
  int tid = threadIdx.x, wid = tid>>5, lane = tid&31;
  float mv = (tid < L_) ? mask[b*L_ + tid] : -3.0e38f;
  float m = block_max(mv, red, wid, lane, 24);
  float e = (tid < L_) ? expf(mv - m) : 0.f;
  float ssum = block_sum(e, red, wid, lane, 24);
  if (tid < L_) s_att[tid] = e / ssum;
  __syncthreads();
  float acc = 0.f;
  int l0 = ch*32;
  const float* hb = hs + ((size_t)b*L_ + l0)*D_ + tid;
  #pragma unroll 4
  for (int l = 0; l < 32; l++)
    acc += s_att[l0+l] * hb[(size_t)l*D_];
  atomicAdd(&g_sent[b*D_ + tid], acc);
}

// ---------------------------------------------------------------------------
// q[b,u] = sentences[b]·Wq[u,:]   grid (B, 8), 256 threads; warp per 4 u's
__global__ void __launch_bounds__(256) k_q(const float* __restrict__ Wq){
  __shared__ float s_sent[D_];
  int b = blockIdx.x, ch = blockIdx.y;
  int tid = threadIdx.x, wid = tid>>5, lane = tid&31;
  for (int i = tid; i < D_; i += 256) s_sent[i] = g_sent[b*D_ + i];
  __syncthreads();
  #pragma unroll
  for (int i = 0; i < 4; i++){
    int u = ch*32 + wid*4 + i;
    const float* wr = Wq + (size_t)u*D_;
    float acc = 0.f;
    #pragma unroll 6
    for (int k = lane; k < D_; k += 32) acc += s_sent[k]*wr[k];
    acc = warp_sum(acc);
    if (lane==0) g_q[b*U_ + u] = acc;
  }
}

// ---------------------------------------------------------------------------
// t[b,h,d] = sum_j q[b,h*64+j]*Wk[h*64+j,d]   grid (B, NH, 6), 128 threads
__global__ void __launch_bounds__(128) k_t(const float* __restrict__ Wk){
  __shared__ float s_q[HD_];
  int b = blockIdx.x, h = blockIdx.y, z = blockIdx.z;
  int tid = threadIdx.x;
  if (tid < HD_) s_q[tid] = g_q[b*U_ + h*HD_ + tid];
  __syncthreads();
  int d = z*128 + tid;
  const float* wk = Wk + (size_t)h*HD_*D_ + d;
  float acc = 0.f;
  #pragma unroll 8
  for (int j = 0; j < HD_; j++)
    acc += s_q[j] * wk[(size_t)j*D_];
  g_t[(b*NH_+h)*D_ + d] = acc;
}

// ---------------------------------------------------------------------------
// scores[b,h,l] = (t[b,h]·hidden[b,l]) / sqrt(D), masked -> -inf
// grid (B, 16), 512 threads; warp per l (each warp does 2 l's)
__global__ void __launch_bounds__(512) k_scores(const float* __restrict__ hs,
                                                const float* __restrict__ mask){
  __shared__ __align__(16) float s_t[NH_*D_];
  int b = blockIdx.x, ch = blockIdx.y;
  int tid = threadIdx.x, wid = tid>>5, lane = tid&31;
  for (int i = tid; i < NH_*D_; i += 512) s_t[i] = g_t[b*NH_*D_ + i];
  __syncthreads();
  const float4* t4 = (const float4*)s_t;
  const float inv_sqrt_d = 0.03608439182435161f; // 1/sqrt(768)
  #pragma unroll
  for (int li = 0; li < 2; li++){
    int l = ch*32 + wid*2 + li;
    const float4* hr = (const float4*)(hs + ((size_t)b*L_ + l)*D_);
    float a0=0.f,a1=0.f,a2=0.f,a3=0.f;
    #pragma unroll
    for (int k = 0; k < 6; k++){
      float4 v  = hr[lane + 32*k];
      float4 t0 = t4[0*192 + lane + 32*k];
      float4 t1 = t4[1*192 + lane + 32*k];
      float4 t2 = t4[2*192 + lane + 32*k];
      float4 t3 = t4[3*192 + lane + 32*k];
      a0 += v.x*t0.x + v.y*t0.y + v.z*t0.z + v.w*t0.w;
      a1 += v.x*t1.x + v.y*t1.y + v.z*t1.z + v.w*t1.w;
      a2 += v.x*t2.x + v.y*t2.y + v.z*t2.z + v.w*t2.w;
      a3 += v.x*t3.x + v.y*t3.y + v.z*t3.z + v.w*t3.w;
    }
    a0 = warp_sum(a0); a1 = warp_sum(a1); a2 = warp_sum(a2); a3 = warp_sum(a3);
    if (lane == 0){
      bool pad = mask[b*L_ + l] < -10.f;
      g_scores[(b*NH_+0)*L_ + l] = pad ? -INFINITY : a0*inv_sqrt_d;
      g_scores[(b*NH_+1)*L_ + l] = pad ? -INFINITY : a1*inv_sqrt_d;
      g_scores[(b*NH_+2)*L_ + l] = pad ? -INFINITY : a2*inv_sqrt_d;
      g_scores[(b*NH_+3)*L_ + l] = pad ? -INFINITY : a3*inv_sqrt_d;
    }
  }
}

// ---------------------------------------------------------------------------
// p[b,h,:] = softmax(scores[b,h,:])   grid B, 512 threads
__global__ void __launch_bounds__(512) k_softmax(){
  __shared__ float red[32];
  int b = blockIdx.x, tid = threadIdx.x, wid = tid>>5, lane = tid&31;
  #pragma unroll
  for (int h = 0; h < NH_; h++){
    float v = g_scores[(b*NH_+h)*L_ + tid];
    float m = block_max(v, red, wid, lane, 16);
    float e = expf(v - m);
    float ssum = block_sum(e, red, wid, lane, 16);
    g_p[(b*NH_+h)*L_ + tid] = e / ssum;
  }
}

// ---------------------------------------------------------------------------
// w[b,h,d] += sum_{l in chunk} p[b,h,l]*hidden[b,l,d]
// grid (B, 32), 768 threads; chunk = 16 l's
__global__ void __launch_bounds__(768) k_wacc(const float* __restrict__ hs){
  __shared__ float s_p[NH_][16];
  int b = blockIdx.x, ch = blockIdx.y;
  int tid = threadIdx.x;
  int l0 = ch*16;
  if (tid < NH_*16){
    int h = tid >> 4, l = tid & 15;
    s_p[h][l] = g_p[(b*NH_+h)*L_ + l0 + l];
  }
  __syncthreads();
  float a0=0.f,a1=0.f,a2=0.f,a3=0.f;
  const float* hb = hs + ((size_t)b*L_ + l0)*D_ + tid;
  #pragma unroll 4
  for (int l = 0; l < 16; l++){
    float hv = hb[(size_t)l*D_];
    a0 += s_p[0][l]*hv;
    a1 += s_p[1][l]*hv;
    a2 += s_p[2][l]*hv;
    a3 += s_p[3][l]*hv;
  }
  atomicAdd(&g_w[(b*NH_+0)*D_ + tid], a0);
  atomicAdd(&g_w[(b*NH_+1)*D_ + tid], a1);
  atomicAdd(&g_w[(b*NH_+2)*D_ + tid], a2);
  atomicAdd(&g_w[(b*NH_+3)*D_ + tid], a3);
}

// ---------------------------------------------------------------------------
// o[b,u] = w[b,h(u)]·Wv[u,:]   grid (B, 8), 256 threads; warp per 4 u's
__global__ void __launch_bounds__(256) k_o(const float* __restrict__ Wv){
  __shared__ float s_w[NH_*D_];
  int b = blockIdx.x, ch = blockIdx.y;
  int tid = threadIdx.x, wid = tid>>5, lane = tid&31;
  for (int i = tid; i < NH_*D_; i += 256) s_w[i] = g_w[b*NH_*D_ + i];
  __syncthreads();
  #pragma unroll
  for (int i = 0; i < 4; i++){
    int u = ch*32 + wid*4 + i;
    int h = u >> 6;
    const float* vr = Wv + (size_t)u*D_;
    float acc = 0.f;
    #pragma unroll 6
    for (int k = lane; k < D_; k += 32) acc += s_w[h*D_ + k]*vr[k];
    acc = warp_sum(acc);
    if (lane==0) g_o[b*U_ + u] = acc;
  }
}

// ---------------------------------------------------------------------------
// new_token[b,d] = o[b,:]·Wo[d,:] + bo[d]   grid (B, 6), 256 threads; warp per d
__global__ void __launch_bounds__(256) k_newtok(const float* __restrict__ Wo,
                                                const float* __restrict__ bo){
  __shared__ float s_o[U_];
  int b = blockIdx.x, ch = blockIdx.y;
  int tid = threadIdx.x, wid = tid>>5, lane = tid&31;
  if (tid < U_) s_o[tid] = g_o[b*U_ + tid];
  __syncthreads();
  #pragma unroll
  for (int i = 0; i < 16; i++){
    int d = ch*128 + wid*16 + i;
    const float* wr = Wo + (size_t)d*U_;
    float acc = 0.f;
    #pragma unroll
    for (int k = lane; k < U_; k += 32) acc += s_o[k]*wr[k];
    acc = warp_sum(acc);
    if (lane==0) g_newtok[b*D_ + d] = acc + bo[d];
  }
}

// ---------------------------------------------------------------------------
// top-K by rank with jax tie rule (greater value wins; ties -> lower index),
// output compacted by index => already index-sorted. grid B, 512 threads.
__global__ void __launch_bounds__(512) k_topk(){
  __shared__ float v[L_];
  __shared__ int flag[L_];
  int b = blockIdx.x, tid = threadIdx.x;
  v[tid] = g_importance[b*L_ + tid];
  __syncthreads();
  float mv = v[tid];
  int r = 0;
  #pragma unroll 8
  for (int j = 0; j < L_; j++){
    float o = v[j];
    r += (o > mv) || (o == mv && j < tid);
  }
  int sel = (r < K_) ? 1 : 0;
  flag[tid] = sel;
  __syncthreads();
  if (sel){
    int pos = 0;
    for (int j = 0; j < tid; j++) pos += flag[j];
    g_idx[b*K_ + pos] = tid;
  }
}

// ---------------------------------------------------------------------------
// Assemble: final_token (B,130,768) then final_attention_mask (B,130).
// grid B*130, 192 threads (float4 rows).
__global__ void __launch_bounds__(192) k_assemble(const float* __restrict__ hs,
                                                  const float* __restrict__ mask,
                                                  float* __restrict__ out){
  int r = blockIdx.x % 130;
  int b = blockIdx.x / 130;
  int tid = threadIdx.x;
  const float* src;
  float mval = 0.f;
  if (r == 0){
    src = hs + (size_t)b*L_*D_;
  } else if (r < 129){
    int idx = g_idx[b*K_ + r - 1];
    src = hs + ((size_t)b*L_ + idx)*D_;
    mval = mask[b*L_ + idx];
  } else {
    src = g_newtok + b*D_;
  }
  float4 val = ((const float4*)src)[tid];
  ((float4*)(out + (size_t)(b*130 + r)*D_))[tid] = val;
  if (tid == 0) out[(size_t)B_*130*D_ + b*130 + r] = mval;
}

// ---------------------------------------------------------------------------
extern "C" void kernel_launch(void* const* d_in, const int* in_sizes, int n_in,
                              void* d_out, int out_size) {
  const float* hs   = (const float*)d_in[0]; // hidden_states (B,L,D)
  const float* mask = (const float*)d_in[1]; // attention_mask (B,1,1,L)
  const float* sas  = (const float*)d_in[2]; // self_attention_scores (B,H,L,L)
  const float* Wq   = (const float*)d_in[3];
  const float* Wk   = (const float*)d_in[4];
  const float* Wv   = (const float*)d_in[5];
  const float* Wo   = (const float*)d_in[6];
  const float* bo   = (const float*)d_in[7];
  float* out = (float*)d_out;

  k_init<<<192, 256>>>();
  k_importance<<<dim3(B_, 96), 256>>>(sas);
  k_sentences<<<dim3(B_, 16), 768>>>(hs, mask);
  k_q<<<dim3(B_, 8), 256>>>(Wq);
  k_t<<<dim3(B_, NH_, 6), 128>>>(Wk);
  k_scores<<<dim3(B_, 16), 512>>>(hs, mask);
  k_softmax<<<B_, 512>>>();
  k_wacc<<<dim3(B_, 32), 768>>>(hs);
  k_o<<<dim3(B_, 8), 256>>>(Wv);
  k_newtok<<<dim3(B_, 6), 256>>>(Wo, bo);
  k_topk<<<B_, 512>>>();
  k_assemble<<<B_*130, 192>>>(hs, mask, out);
}

// round 4
// speedup vs baseline: 1.7591x; 1.3051x over previous
#include <cuda_runtime.h>
#include <math.h>

// Problem constants
#define B_ 16
#define L_ 512
#define D_ 768
#define H_ 12
#define K_ 128
#define U_ 256
#define NH_ 4
#define HD_ 64

static __device__ __align__(16) float g_importance[B_*L_];
static __device__ __align__(16) float g_att[B_*L_];
static __device__ __align__(16) float g_sent[B_*D_];
static __device__ __align__(16) float g_t[B_*NH_*D_];
static __device__ __align__(16) float g_scores[B_*NH_*L_];
static __device__ __align__(16) float g_p[B_*NH_*L_];
static __device__ __align__(16) float g_w[B_*NH_*D_];
static __device__ __align__(16) float g_o[B_*U_];
static __device__ __align__(16) float g_newtok[B_*D_];
static __device__ int   g_idx[B_*K_];

__device__ __forceinline__ float warp_max(float v){
  #pragma unroll
  for (int o=16;o;o>>=1) v = fmaxf(v, __shfl_xor_sync(0xffffffffu, v, o));
  return v;
}
__device__ __forceinline__ float warp_sum(float v){
  #pragma unroll
  for (int o=16;o;o>>=1) v += __shfl_xor_sync(0xffffffffu, v, o);
  return v;
}
__device__ __forceinline__ float block_max(float v, float* red, int wid, int lane, int nw){
  v = warp_max(v);
  if (lane==0) red[wid] = v;
  __syncthreads();
  if (wid==0){
    float x = (lane < nw) ? red[lane] : -INFINITY;
    x = warp_max(x);
    if (lane==0) red[0] = x;
  }
  __syncthreads();
  float r = red[0];
  __syncthreads();
  return r;
}
__device__ __forceinline__ float block_sum(float v, float* red, int wid, int lane, int nw){
  v = warp_sum(v);
  if (lane==0) red[wid] = v;
  __syncthreads();
  if (wid==0){
    float x = (lane < nw) ? red[lane] : 0.f;
    x = warp_sum(x);
    if (lane==0) red[0] = x;
  }
  __syncthreads();
  float r = red[0];
  __syncthreads();
  return r;
}
__device__ __forceinline__ float dot4(float4 a, float4 b){
  return a.x*b.x + a.y*b.y + a.z*b.z + a.w*b.w;
}

// ---------------------------------------------------------------------------
// Zero accumulators (required every graph replay)
__global__ void __launch_bounds__(256) k_init(){
  int i = blockIdx.x*blockDim.x + threadIdx.x;
  if (i < B_*L_)     g_importance[i] = 0.f;
  if (i < B_*D_)     g_sent[i] = 0.f;
  if (i < B_*NH_*D_) g_w[i] = 0.f;
}

// ---------------------------------------------------------------------------
// importance[b,l] = (1/H) * sum_{h,q} scores[b,h,q,l]   (201 MB streaming reduce)
// grid (B, 96): each block sums 64 of the 6144 (h,q) rows.
__global__ void __launch_bounds__(256) k_importance(const float* __restrict__ s){
  int b = blockIdx.x, ch = blockIdx.y;
  int col = threadIdx.x & 127;
  int rh  = threadIdx.x >> 7;
  const float4* base = (const float4*)s + (size_t)(b*H_*L_ + ch*64) * (L_/4);
  float4 acc = make_float4(0.f,0.f,0.f,0.f);
  #pragma unroll 8
  for (int r = rh; r < 64; r += 2){
    float4 v = base[(size_t)r*(L_/4) + col];
    acc.x += v.x; acc.y += v.y; acc.z += v.z; acc.w += v.w;
  }
  const float sc = 1.0f/(float)H_;
  float* out = g_importance + b*L_ + col*4;
  atomicAdd(out+0, acc.x*sc);
  atomicAdd(out+1, acc.y*sc);
  atomicAdd(out+2, acc.z*sc);
  atomicAdd(out+3, acc.w*sc);
}

// ---------------------------------------------------------------------------
// att[b,:] = softmax(mask[b,:])   grid B, 512 threads
__global__ void __launch_bounds__(512) k_att(const float* __restrict__ mask){
  __shared__ float red[32];
  int b = blockIdx.x, tid = threadIdx.x, wid = tid>>5, lane = tid&31;
  float mv = mask[b*L_ + tid];
  float m = block_max(mv, red, wid, lane, 16);
  float e = expf(mv - m);
  float ssum = block_sum(e, red, wid, lane, 16);
  g_att[b*L_ + tid] = e / ssum;
}

// ---------------------------------------------------------------------------
// sentences[b,d] = sum_l att[b,l] * hidden[b,l,d]
// grid (B, 32), 768 threads; 16 l's per block, atomic accumulate.
__global__ void __launch_bounds__(768) k_sentences(const float* __restrict__ hs){
  __shared__ float s_att[16];
  int b = blockIdx.x, ch = blockIdx.y;
  int tid = threadIdx.x;
  int l0 = ch*16;
  if (tid < 16) s_att[tid] = g_att[b*L_ + l0 + tid];
  __syncthreads();
  float acc = 0.f;
  const float* hb = hs + ((size_t)b*L_ + l0)*D_ + tid;
  #pragma unroll 4
  for (int l = 0; l < 16; l++)
    acc += s_att[l] * hb[(size_t)l*D_];
  atomicAdd(&g_sent[b*D_ + tid], acc);
}

// ---------------------------------------------------------------------------
// Fused q+t per (b,h): q_j = sent·Wq[h*64+j]; t[b,h,d] = sum_j q_j*Wk[h*64+j,d]
// grid (B, NH), 256 threads
__global__ void __launch_bounds__(256) k_qt(const float* __restrict__ Wq,
                                            const float* __restrict__ Wk){
  __shared__ __align__(16) float s_sent[D_];
  __shared__ float s_q[HD_];
  int b = blockIdx.x, h = blockIdx.y;
  int tid = threadIdx.x, wid = tid>>5, lane = tid&31;
  // load sentence vector (192 float4)
  if (tid < 192) ((float4*)s_sent)[tid] = ((const float4*)(g_sent + b*D_))[tid];
  __syncthreads();
  const float4* s4 = (const float4*)s_sent;
  // phase 1: 8 warps x 8 j's -> q
  #pragma unroll
  for (int jj = 0; jj < 8; jj++){
    int j = wid*8 + jj;
    const float4* wr = (const float4*)(Wq + (size_t)(h*HD_ + j)*D_);
    float acc = 0.f;
    #pragma unroll
    for (int k = 0; k < 6; k++) acc += dot4(s4[lane + 32*k], wr[lane + 32*k]);
    acc = warp_sum(acc);
    if (lane==0) s_q[j] = acc;
  }
  __syncthreads();
  // phase 2: 192 threads, one float4 column of t each
  if (tid < 192){
    const float4* wk = (const float4*)(Wk + (size_t)h*HD_*D_) + tid;
    float4 acc = make_float4(0.f,0.f,0.f,0.f);
    #pragma unroll 8
    for (int j = 0; j < HD_; j++){
      float qj = s_q[j];
      float4 v = wk[(size_t)j*192];
      acc.x += qj*v.x; acc.y += qj*v.y; acc.z += qj*v.z; acc.w += qj*v.w;
    }
    ((float4*)(g_t + (b*NH_+h)*D_))[tid] = acc;
  }
}

// ---------------------------------------------------------------------------
// scores[b,h,l] = (t[b,h]·hidden[b,l]) / sqrt(D), masked -> -inf
// grid (B, 32), 512 threads (16 warps); warp per l
__global__ void __launch_bounds__(512) k_scores(const float* __restrict__ hs,
                                                const float* __restrict__ mask){
  __shared__ __align__(16) float s_t[NH_*D_];
  int b = blockIdx.x, ch = blockIdx.y;
  int tid = threadIdx.x, wid = tid>>5, lane = tid&31;
  for (int i = tid; i < NH_*192; i += 512)
    ((float4*)s_t)[i] = ((const float4*)(g_t + b*NH_*D_))[i];
  __syncthreads();
  const float4* t4 = (const float4*)s_t;
  const float inv_sqrt_d = 0.03608439182435161f; // 1/sqrt(768)
  int l = ch*16 + wid;
  const float4* hr = (const float4*)(hs + ((size_t)b*L_ + l)*D_);
  float a0=0.f,a1=0.f,a2=0.f,a3=0.f;
  #pragma unroll
  for (int k = 0; k < 6; k++){
    float4 v  = hr[lane + 32*k];
    a0 += dot4(v, t4[0*192 + lane + 32*k]);
    a1 += dot4(v, t4[1*192 + lane + 32*k]);
    a2 += dot4(v, t4[2*192 + lane + 32*k]);
    a3 += dot4(v, t4[3*192 + lane + 32*k]);
  }
  a0 = warp_sum(a0); a1 = warp_sum(a1); a2 = warp_sum(a2); a3 = warp_sum(a3);
  if (lane == 0){
    bool pad = mask[b*L_ + l] < -10.f;
    g_scores[(b*NH_+0)*L_ + l] = pad ? -INFINITY : a0*inv_sqrt_d;
    g_scores[(b*NH_+1)*L_ + l] = pad ? -INFINITY : a1*inv_sqrt_d;
    g_scores[(b*NH_+2)*L_ + l] = pad ? -INFINITY : a2*inv_sqrt_d;
    g_scores[(b*NH_+3)*L_ + l] = pad ? -INFINITY : a3*inv_sqrt_d;
  }
}

// ---------------------------------------------------------------------------
// p[b,h,:] = softmax(scores[b,h,:])   grid (B, NH), 512 threads
__global__ void __launch_bounds__(512) k_softmax(){
  __shared__ float red[32];
  int b = blockIdx.x, h = blockIdx.y;
  int tid = threadIdx.x, wid = tid>>5, lane = tid&31;
  float v = g_scores[(b*NH_+h)*L_ + tid];
  float m = block_max(v, red, wid, lane, 16);
  float e = expf(v - m);
  float ssum = block_sum(e, red, wid, lane, 16);
  g_p[(b*NH_+h)*L_ + tid] = e / ssum;
}

// ---------------------------------------------------------------------------
// w[b,h,d] += sum_{l in chunk} p[b,h,l]*hidden[b,l,d]
// grid (B, 32), 768 threads; chunk = 16 l's
__global__ void __launch_bounds__(768) k_wacc(const float* __restrict__ hs){
  __shared__ float s_p[NH_][16];
  int b = blockIdx.x, ch = blockIdx.y;
  int tid = threadIdx.x;
  int l0 = ch*16;
  if (tid < NH_*16){
    int h = tid >> 4, l = tid & 15;
    s_p[h][l] = g_p[(b*NH_+h)*L_ + l0 + l];
  }
  __syncthreads();
  float a0=0.f,a1=0.f,a2=0.f,a3=0.f;
  const float* hb = hs + ((size_t)b*L_ + l0)*D_ + tid;
  #pragma unroll 4
  for (int l = 0; l < 16; l++){
    float hv = hb[(size_t)l*D_];
    a0 += s_p[0][l]*hv;
    a1 += s_p[1][l]*hv;
    a2 += s_p[2][l]*hv;
    a3 += s_p[3][l]*hv;
  }
  atomicAdd(&g_w[(b*NH_+0)*D_ + tid], a0);
  atomicAdd(&g_w[(b*NH_+1)*D_ + tid], a1);
  atomicAdd(&g_w[(b*NH_+2)*D_ + tid], a2);
  atomicAdd(&g_w[(b*NH_+3)*D_ + tid], a3);
}

// ---------------------------------------------------------------------------
// o[b,u] = w[b,h(u)]·Wv[u,:]   grid (B, 32), 256 threads; warp per u
__global__ void __launch_bounds__(256) k_o(const float* __restrict__ Wv){
  __shared__ __align__(16) float s_w[NH_*D_];
  int b = blockIdx.x, ch = blockIdx.y;
  int tid = threadIdx.x, wid = tid>>5, lane = tid&31;
  for (int i = tid; i < NH_*192; i += 256)
    ((float4*)s_w)[i] = ((const float4*)(g_w + b*NH_*D_))[i];
  __syncthreads();
  int u = ch*8 + wid;
  int h = u >> 6;
  const float4* vr = (const float4*)(Wv + (size_t)u*D_);
  const float4* w4 = (const float4*)(s_w + h*D_);
  float acc = 0.f;
  #pragma unroll
  for (int k = 0; k < 6; k++) acc += dot4(w4[lane + 32*k], vr[lane + 32*k]);
  acc = warp_sum(acc);
  if (lane==0) g_o[b*U_ + u] = acc;
}

// ---------------------------------------------------------------------------
// new_token[b,d] = o[b,:]·Wo[d,:] + bo[d]   grid (B, 96), 256 threads; warp per d... 8 warps -> d=ch*8+wid
__global__ void __launch_bounds__(256) k_newtok(const float* __restrict__ Wo,
                                                const float* __restrict__ bo){
  __shared__ __align__(16) float s_o[U_];
  int b = blockIdx.x, ch = blockIdx.y;
  int tid = threadIdx.x, wid = tid>>5, lane = tid&31;
  if (tid < 64) ((float4*)s_o)[tid] = ((const float4*)(g_o + b*U_))[tid];
  __syncthreads();
  int d = ch*8 + wid;
  const float4* wr = (const float4*)(Wo + (size_t)d*U_);
  const float4* o4 = (const float4*)s_o;
  float acc = 0.f;
  #pragma unroll
  for (int k = 0; k < 2; k++) acc += dot4(o4[lane + 32*k], wr[lane + 32*k]);
  acc = warp_sum(acc);
  if (lane==0) g_newtok[b*D_ + d] = acc + bo[d];
}

// ---------------------------------------------------------------------------
// top-K by rank with jax tie rule (greater value wins; ties -> lower index),
// output compacted by index => already index-sorted. grid B, 512 threads.
__global__ void __launch_bounds__(512) k_topk(){
  __shared__ float v[L_];
  __shared__ int flag[L_];
  int b = blockIdx.x, tid = threadIdx.x;
  v[tid] = g_importance[b*L_ + tid];
  __syncthreads();
  float mv = v[tid];
  int r = 0;
  #pragma unroll 8
  for (int j = 0; j < L_; j++){
    float o = v[j];
    r += (o > mv) || (o == mv && j < tid);
  }
  int sel = (r < K_) ? 1 : 0;
  flag[tid] = sel;
  __syncthreads();
  if (sel){
    int pos = 0;
    for (int j = 0; j < tid; j++) pos += flag[j];
    g_idx[b*K_ + pos] = tid;
  }
}

// ---------------------------------------------------------------------------
// Assemble: final_token (B,130,768) then final_attention_mask (B,130).
// grid B*130, 192 threads (float4 rows).
__global__ void __launch_bounds__(192) k_assemble(const float* __restrict__ hs,
                                                  const float* __restrict__ mask,
                                                  float* __restrict__ out){
  int r = blockIdx.x % 130;
  int b = blockIdx.x / 130;
  int tid = threadIdx.x;
  const float* src;
  float mval = 0.f;
  if (r == 0){
    src = hs + (size_t)b*L_*D_;
  } else if (r < 129){
    int idx = g_idx[b*K_ + r - 1];
    src = hs + ((size_t)b*L_ + idx)*D_;
    mval = mask[b*L_ + idx];
  } else {
    src = g_newtok + b*D_;
  }
  float4 val = ((const float4*)src)[tid];
  ((float4*)(out + (size_t)(b*130 + r)*D_))[tid] = val;
  if (tid == 0) out[(size_t)B_*130*D_ + b*130 + r] = mval;
}

// ---------------------------------------------------------------------------
extern "C" void kernel_launch(void* const* d_in, const int* in_sizes, int n_in,
                              void* d_out, int out_size) {
  const float* hs   = (const float*)d_in[0]; // hidden_states (B,L,D)
  const float* mask = (const float*)d_in[1]; // attention_mask (B,1,1,L)
  const float* sas  = (const float*)d_in[2]; // self_attention_scores (B,H,L,L)
  const float* Wq   = (const float*)d_in[3];
  const float* Wk   = (const float*)d_in[4];
  const float* Wv   = (const float*)d_in[5];
  const float* Wo   = (const float*)d_in[6];
  const float* bo   = (const float*)d_in[7];
  float* out = (float*)d_out;

  // Lazy-create side stream + events (first call is NOT captured; graph
  // capture on later calls re-uses them via the standard fork/join pattern).
  static cudaStream_t s2 = 0;
  static cudaEvent_t ev_fork = 0, ev_join = 0;
  if (!s2){
    cudaStreamCreateWithFlags(&s2, cudaStreamNonBlocking);
    cudaEventCreateWithFlags(&ev_fork, cudaEventDisableTiming);
    cudaEventCreateWithFlags(&ev_join, cudaEventDisableTiming);
  }

  k_init<<<192, 256>>>();

  // fork: importance/topk chain on s2 (DRAM-bound), attention chain on default
  cudaEventRecord(ev_fork, 0);
  cudaStreamWaitEvent(s2, ev_fork, 0);
  k_importance<<<dim3(B_, 96), 256, 0, s2>>>(sas);
  k_topk<<<B_, 512, 0, s2>>>();
  cudaEventRecord(ev_join, s2);

  k_att<<<B_, 512>>>(mask);
  k_sentences<<<dim3(B_, 32), 768>>>(hs);
  k_qt<<<dim3(B_, NH_), 256>>>(Wq, Wk);
  k_scores<<<dim3(B_, 32), 512>>>(hs, mask);
  k_softmax<<<dim3(B_, NH_), 512>>>();
  k_wacc<<<dim3(B_, 32), 768>>>(hs);
  k_o<<<dim3(B_, 32), 256>>>(Wv);
  k_newtok<<<dim3(B_, 96), 256>>>(Wo, bo);

  // join
  cudaStreamWaitEvent(0, ev_join, 0);
  k_assemble<<<B_*130, 192>>>(hs, mask, out);
}

// round 5
// speedup vs baseline: 1.7930x; 1.0193x over previous
#include <cuda_runtime.h>
#include <math.h>

// Problem constants
#define B_ 16
#define L_ 512
#define D_ 768
#define H_ 12
#define K_ 128
#define U_ 256
#define NH_ 4
#define HD_ 64

// Partial-sum scratch (no init needed: fully overwritten every replay)
static __device__ __align__(16) float g_imp_part[B_*24*L_];     // (b, chunk24, l)
static __device__ __align__(16) float g_sent_part[B_*16*D_];    // (b, chunk16, d)
static __device__ __align__(16) float g_t[B_*NH_*D_];
static __device__ __align__(16) float g_scores[B_*NH_*L_];
static __device__ __align__(16) float g_w_part[B_*16*NH_*D_];   // (b, chunk16, h, d)
static __device__ __align__(16) float g_newtok[B_*D_];
static __device__ int   g_idx[B_*K_];

__device__ __forceinline__ float warp_max(float v){
  #pragma unroll
  for (int o=16;o;o>>=1) v = fmaxf(v, __shfl_xor_sync(0xffffffffu, v, o));
  return v;
}
__device__ __forceinline__ float warp_sum(float v){
  #pragma unroll
  for (int o=16;o;o>>=1) v += __shfl_xor_sync(0xffffffffu, v, o);
  return v;
}
__device__ __forceinline__ float block_max(float v, float* red, int wid, int lane, int nw){
  v = warp_max(v);
  if (lane==0) red[wid] = v;
  __syncthreads();
  if (wid==0){
    float x = (lane < nw) ? red[lane] : -INFINITY;
    x = warp_max(x);
    if (lane==0) red[0] = x;
  }
  __syncthreads();
  float r = red[0];
  __syncthreads();
  return r;
}
__device__ __forceinline__ float block_sum(float v, float* red, int wid, int lane, int nw){
  v = warp_sum(v);
  if (lane==0) red[wid] = v;
  __syncthreads();
  if (wid==0){
    float x = (lane < nw) ? red[lane] : 0.f;
    x = warp_sum(x);
    if (lane==0) red[0] = x;
  }
  __syncthreads();
  float r = red[0];
  __syncthreads();
  return r;
}
__device__ __forceinline__ float dot4(float4 a, float4 b){
  return a.x*b.x + a.y*b.y + a.z*b.z + a.w*b.w;
}

// ---------------------------------------------------------------------------
// importance partials: g_imp_part[b,ch,l] = (1/H)*sum_{r in chunk} sas[b, rows, l]
// grid (B, 24), 256 threads: 256 (h,q)-rows per block, 128 float4 cols x 2 row-halves.
__global__ void __launch_bounds__(256) k_importance(const float* __restrict__ s){
  __shared__ float4 s_half[128];
  int b = blockIdx.x, ch = blockIdx.y;
  int col = threadIdx.x & 127;
  int rh  = threadIdx.x >> 7;
  const float4* base = (const float4*)s + (size_t)(b*H_*L_ + ch*256) * (L_/4);
  float4 acc = make_float4(0.f,0.f,0.f,0.f);
  #pragma unroll 8
  for (int r = rh; r < 256; r += 2){
    float4 v = base[(size_t)r*(L_/4) + col];
    acc.x += v.x; acc.y += v.y; acc.z += v.z; acc.w += v.w;
  }
  if (rh == 1) s_half[col] = acc;
  __syncthreads();
  if (rh == 0){
    const float sc = 1.0f/(float)H_;
    float4 o = s_half[col];
    o.x = (o.x + acc.x)*sc; o.y = (o.y + acc.y)*sc;
    o.z = (o.z + acc.z)*sc; o.w = (o.w + acc.w)*sc;
    ((float4*)(g_imp_part + (size_t)(b*24 + ch)*L_))[col] = o;
  }
}

// ---------------------------------------------------------------------------
// top-K: reduce 24 partials, rank with jax tie rule, compact by index.
__global__ void __launch_bounds__(512) k_topk(){
  __shared__ float v[L_];
  __shared__ int flag[L_];
  int b = blockIdx.x, tid = threadIdx.x;
  float acc = 0.f;
  #pragma unroll
  for (int c = 0; c < 24; c++)
    acc += g_imp_part[(size_t)(b*24 + c)*L_ + tid];
  v[tid] = acc;
  __syncthreads();
  float mv = v[tid];
  int r = 0;
  #pragma unroll 8
  for (int j = 0; j < L_; j++){
    float o = v[j];
    r += (o > mv) || (o == mv && j < tid);
  }
  int sel = (r < K_) ? 1 : 0;
  flag[tid] = sel;
  __syncthreads();
  if (sel){
    int pos = 0;
    for (int j = 0; j < tid; j++) pos += flag[j];
    g_idx[b*K_ + pos] = tid;
  }
}

// ---------------------------------------------------------------------------
// Fused mask-softmax + sentence partials.
// grid (B, 16), 768 threads; each block recomputes softmax(mask[b,:]) then
// accumulates 32 l's into g_sent_part[b,ch,:].
__global__ void __launch_bounds__(768) k_sent(const float* __restrict__ hs,
                                              const float* __restrict__ mask){
  __shared__ float s_att[L_];
  __shared__ float red[32];
  int b = blockIdx.x, ch = blockIdx.y;
  int tid = threadIdx.x, wid = tid>>5, lane = tid&31;
  float mv = (tid < L_) ? mask[b*L_ + tid] : -INFINITY;
  float m = block_max(mv, red, wid, lane, 24);
  float e = (tid < L_) ? expf(mv - m) : 0.f;
  float ssum = block_sum(e, red, wid, lane, 24);
  if (tid < L_) s_att[tid] = e / ssum;
  __syncthreads();
  float acc = 0.f;
  int l0 = ch*32;
  const float* hb = hs + ((size_t)b*L_ + l0)*D_ + tid;
  #pragma unroll 4
  for (int l = 0; l < 32; l++)
    acc += s_att[l0+l] * hb[(size_t)l*D_];
  g_sent_part[(size_t)(b*16 + ch)*D_ + tid] = acc;
}

// ---------------------------------------------------------------------------
// Fused q+t per (b,h): reduce sentence partials, q_j = sent·Wq_row, t = q·Wk_rows
// grid (B, NH), 256 threads
__global__ void __launch_bounds__(256) k_qt(const float* __restrict__ Wq,
                                            const float* __restrict__ Wk){
  __shared__ __align__(16) float s_sent[D_];
  __shared__ float s_q[HD_];
  int b = blockIdx.x, h = blockIdx.y;
  int tid = threadIdx.x, wid = tid>>5, lane = tid&31;
  if (tid < 192){
    float4 a = make_float4(0.f,0.f,0.f,0.f);
    #pragma unroll
    for (int c = 0; c < 16; c++){
      float4 v = ((const float4*)(g_sent_part + (size_t)(b*16 + c)*D_))[tid];
      a.x += v.x; a.y += v.y; a.z += v.z; a.w += v.w;
    }
    ((float4*)s_sent)[tid] = a;
  }
  __syncthreads();
  const float4* s4 = (const float4*)s_sent;
  #pragma unroll
  for (int jj = 0; jj < 8; jj++){
    int j = wid*8 + jj;
    const float4* wr = (const float4*)(Wq + (size_t)(h*HD_ + j)*D_);
    float acc = 0.f;
    #pragma unroll
    for (int k = 0; k < 6; k++) acc += dot4(s4[lane + 32*k], wr[lane + 32*k]);
    acc = warp_sum(acc);
    if (lane==0) s_q[j] = acc;
  }
  __syncthreads();
  if (tid < 192){
    const float4* wk = (const float4*)(Wk + (size_t)h*HD_*D_) + tid;
    float4 acc = make_float4(0.f,0.f,0.f,0.f);
    #pragma unroll 8
    for (int j = 0; j < HD_; j++){
      float qj = s_q[j];
      float4 v = wk[(size_t)j*192];
      acc.x += qj*v.x; acc.y += qj*v.y; acc.z += qj*v.z; acc.w += qj*v.w;
    }
    ((float4*)(g_t + (b*NH_+h)*D_))[tid] = acc;
  }
}

// ---------------------------------------------------------------------------
// scores[b,h,l] = (t[b,h]·hidden[b,l]) / sqrt(D), masked -> -inf
// grid (B, 32), 512 threads (16 warps); warp per l
__global__ void __launch_bounds__(512) k_scores(const float* __restrict__ hs,
                                                const float* __restrict__ mask){
  __shared__ __align__(16) float s_t[NH_*D_];
  int b = blockIdx.x, ch = blockIdx.y;
  int tid = threadIdx.x, wid = tid>>5, lane = tid&31;
  for (int i = tid; i < NH_*192; i += 512)
    ((float4*)s_t)[i] = ((const float4*)(g_t + b*NH_*D_))[i];
  __syncthreads();
  const float4* t4 = (const float4*)s_t;
  const float inv_sqrt_d = 0.03608439182435161f; // 1/sqrt(768)
  int l = ch*16 + wid;
  const float4* hr = (const float4*)(hs + ((size_t)b*L_ + l)*D_);
  float a0=0.f,a1=0.f,a2=0.f,a3=0.f;
  #pragma unroll
  for (int k = 0; k < 6; k++){
    float4 v  = hr[lane + 32*k];
    a0 += dot4(v, t4[0*192 + lane + 32*k]);
    a1 += dot4(v, t4[1*192 + lane + 32*k]);
    a2 += dot4(v, t4[2*192 + lane + 32*k]);
    a3 += dot4(v, t4[3*192 + lane + 32*k]);
  }
  a0 = warp_sum(a0); a1 = warp_sum(a1); a2 = warp_sum(a2); a3 = warp_sum(a3);
  if (lane == 0){
    bool pad = mask[b*L_ + l] < -10.f;
    g_scores[(b*NH_+0)*L_ + l] = pad ? -INFINITY : a0*inv_sqrt_d;
    g_scores[(b*NH_+1)*L_ + l] = pad ? -INFINITY : a1*inv_sqrt_d;
    g_scores[(b*NH_+2)*L_ + l] = pad ? -INFINITY : a2*inv_sqrt_d;
    g_scores[(b*NH_+3)*L_ + l] = pad ? -INFINITY : a3*inv_sqrt_d;
  }
}

// ---------------------------------------------------------------------------
// Fused softmax + weighted-hidden partials.
// grid (B, 16), 768 threads; block recomputes softmax per head, then
// accumulates its 32 l's -> g_w_part[b,ch,h,:]
__global__ void __launch_bounds__(768) k_wacc(const float* __restrict__ hs){
  __shared__ float s_p[NH_*L_];
  __shared__ float red[32];
  int b = blockIdx.x, ch = blockIdx.y;
  int tid = threadIdx.x, wid = tid>>5, lane = tid&31;
  #pragma unroll
  for (int h = 0; h < NH_; h++){
    float v = (tid < L_) ? g_scores[(b*NH_+h)*L_ + tid] : -INFINITY;
    float m = block_max(v, red, wid, lane, 24);
    float e = (tid < L_) ? expf(v - m) : 0.f;
    float ssum = block_sum(e, red, wid, lane, 24);
    if (tid < L_) s_p[h*L_ + tid] = e / ssum;
  }
  __syncthreads();
  float a0=0.f,a1=0.f,a2=0.f,a3=0.f;
  int l0 = ch*32;
  const float* hb = hs + ((size_t)b*L_ + l0)*D_ + tid;
  #pragma unroll 2
  for (int l = 0; l < 32; l++){
    float hv = hb[(size_t)l*D_];
    a0 += s_p[0*L_ + l0+l]*hv;
    a1 += s_p[1*L_ + l0+l]*hv;
    a2 += s_p[2*L_ + l0+l]*hv;
    a3 += s_p[3*L_ + l0+l]*hv;
  }
  float* wp = g_w_part + (size_t)((b*16 + ch)*NH_)*D_ + tid;
  wp[0*D_] = a0; wp[1*D_] = a1; wp[2*D_] = a2; wp[3*D_] = a3;
}

// ---------------------------------------------------------------------------
// Fused: reduce w partials -> o = w·Wv -> new_token = o·Wo + bo
// grid B, 1024 threads (32 warps)
__global__ void __launch_bounds__(1024) k_out(const float* __restrict__ Wv,
                                              const float* __restrict__ Wo,
                                              const float* __restrict__ bo){
  __shared__ __align__(16) float s_w[NH_*D_];
  __shared__ __align__(16) float s_o[U_];
  int b = blockIdx.x;
  int tid = threadIdx.x, wid = tid>>5, lane = tid&31;
  // reduce 16 w-partials (768 float4 lanes)
  if (tid < NH_*192){
    float4 a = make_float4(0.f,0.f,0.f,0.f);
    #pragma unroll
    for (int c = 0; c < 16; c++){
      float4 v = ((const float4*)(g_w_part + (size_t)((b*16 + c)*NH_)*D_))[tid];
      a.x += v.x; a.y += v.y; a.z += v.z; a.w += v.w;
    }
    ((float4*)s_w)[tid] = a;
  }
  __syncthreads();
  // o[u] = w[h(u)]·Wv[u,:], warp per u, 8 rounds
  #pragma unroll
  for (int i = 0; i < 8; i++){
    int u = i*32 + wid;
    int h = u >> 6;
    const float4* vr = (const float4*)(Wv + (size_t)u*D_);
    const float4* w4 = (const float4*)(s_w + h*D_);
    float acc = 0.f;
    #pragma unroll
    for (int k = 0; k < 6; k++) acc += dot4(w4[lane + 32*k], vr[lane + 32*k]);
    acc = warp_sum(acc);
    if (lane==0) s_o[u] = acc;
  }
  __syncthreads();
  // new_token[d] = o·Wo[d,:] + bo[d], warp per d, 24 rounds
  const float4* o4 = (const float4*)s_o;
  #pragma unroll
  for (int i = 0; i < 24; i++){
    int d = i*32 + wid;
    const float4* wr = (const float4*)(Wo + (size_t)d*U_);
    float acc = dot4(o4[lane], wr[lane]) + dot4(o4[lane+32], wr[lane+32]);
    acc = warp_sum(acc);
    if (lane==0) g_newtok[b*D_ + d] = acc + bo[d];
  }
}

// ---------------------------------------------------------------------------
// Assemble: final_token (B,130,768) then final_attention_mask (B,130).
// grid B*130, 192 threads (float4 rows).
__global__ void __launch_bounds__(192) k_assemble(const float* __restrict__ hs,
                                                  const float* __restrict__ mask,
                                                  float* __restrict__ out){
  int r = blockIdx.x % 130;
  int b = blockIdx.x / 130;
  int tid = threadIdx.x;
  const float* src;
  float mval = 0.f;
  if (r == 0){
    src = hs + (size_t)b*L_*D_;
  } else if (r < 129){
    int idx = g_idx[b*K_ + r - 1];
    src = hs + ((size_t)b*L_ + idx)*D_;
    mval = mask[b*L_ + idx];
  } else {
    src = g_newtok + b*D_;
  }
  float4 val = ((const float4*)src)[tid];
  ((float4*)(out + (size_t)(b*130 + r)*D_))[tid] = val;
  if (tid == 0) out[(size_t)B_*130*D_ + b*130 + r] = mval;
}

// ---------------------------------------------------------------------------
extern "C" void kernel_launch(void* const* d_in, const int* in_sizes, int n_in,
                              void* d_out, int out_size) {
  const float* hs   = (const float*)d_in[0]; // hidden_states (B,L,D)
  const float* mask = (const float*)d_in[1]; // attention_mask (B,1,1,L)
  const float* sas  = (const float*)d_in[2]; // self_attention_scores (B,H,L,L)
  const float* Wq   = (const float*)d_in[3];
  const float* Wk   = (const float*)d_in[4];
  const float* Wv   = (const float*)d_in[5];
  const float* Wo   = (const float*)d_in[6];
  const float* bo   = (const float*)d_in[7];
  float* out = (float*)d_out;

  // Lazy-create side stream + events (first call is NOT captured; graph
  // capture on later calls re-uses them via the fork/join pattern).
  static cudaStream_t s2 = 0;
  static cudaEvent_t ev_fork = 0, ev_join = 0;
  if (!s2){
    cudaStreamCreateWithFlags(&s2, cudaStreamNonBlocking);
    cudaEventCreateWithFlags(&ev_fork, cudaEventDisableTiming);
    cudaEventCreateWithFlags(&ev_join, cudaEventDisableTiming);
  }

  // fork: importance/topk chain (DRAM-bound) on s2
  cudaEventRecord(ev_fork, 0);
  cudaStreamWaitEvent(s2, ev_fork, 0);
  k_importance<<<dim3(B_, 24), 256, 0, s2>>>(sas);
  k_topk<<<B_, 512, 0, s2>>>();
  cudaEventRecord(ev_join, s2);

  // attention chain (latency-bound) on default stream
  k_sent<<<dim3(B_, 16), 768>>>(hs, mask);
  k_qt<<<dim3(B_, NH_), 256>>>(Wq, Wk);
  k_scores<<<dim3(B_, 32), 512>>>(hs, mask);
  k_wacc<<<dim3(B_, 16), 768>>>(hs);
  k_out<<<B_, 1024>>>(Wv, Wo, bo);

  // join
  cudaStreamWaitEvent(0, ev_join, 0);
  k_assemble<<<B_*130, 192>>>(hs, mask, out);
}